// round 1
// baseline (speedup 1.0000x reference)
#include <cuda_runtime.h>

// Problem constants
#define Bb 32
#define Ll 1024
#define Ee 512
#define Oo 512

// GEMM tiling
#define BM 128
#define BN 128
#define BK 16
#define TM 8
#define TN 8
#define NTHREADS 256
#define LDS 132   // BM + 4 pad (keeps 16B alignment: 132*4 = 528, mult of 16)

// Scratch (static __device__ — no allocations allowed)
__device__ float g_q[Bb * Ll * Oo];            // 64 MB
__device__ float g_k[Bb * Ll * Oo];            // 64 MB
__device__ float g_v[Bb * Ll * Oo];            // 64 MB
__device__ float g_s[33554432];                // B*L*L = 128 MB (scores -> attn)

// ---------------------------------------------------------------------------
// Tile loaders. 256 threads, tile BM x BK (A, stored transposed As[k][m]) or
// BK x BN (B, stored Bs[k][n]). All loads are float4.
// ---------------------------------------------------------------------------
__device__ __forceinline__ void load_tileA(const float* __restrict__ src, int lda,
                                           int m0, int k0,
                                           float (*As)[LDS], int tid) {
#pragma unroll
    for (int s = 0; s < 2; ++s) {
        int ff = tid + s * NTHREADS;        // 0..511
        int r  = ff >> 2;                   // 0..127 (tile row)
        int c4 = (ff & 3) << 2;             // 0,4,8,12 (k within tile)
        const float4 v = *(const float4*)(src + (size_t)(m0 + r) * lda + k0 + c4);
        As[c4 + 0][r] = v.x;
        As[c4 + 1][r] = v.y;
        As[c4 + 2][r] = v.z;
        As[c4 + 3][r] = v.w;
    }
}

__device__ __forceinline__ void load_tileB(const float* __restrict__ src, int ldb,
                                           int k0, int n0,
                                           float (*Bs)[LDS], int tid) {
#pragma unroll
    for (int s = 0; s < 2; ++s) {
        int ff = tid + s * NTHREADS;        // 0..511
        int r  = ff >> 5;                   // 0..15 (k within tile)
        int c4 = (ff & 31) << 2;            // 0..124 (n within tile)
        *(float4*)(&Bs[r][c4]) =
            *(const float4*)(src + (size_t)(k0 + r) * ldb + n0 + c4);
    }
}

// 8x8 register microkernel over one BK slice
__device__ __forceinline__ void microkernel(const float (*As)[LDS],
                                            const float (*Bs)[LDS],
                                            int rb, int cb,
                                            float acc[TM][TN]) {
#pragma unroll
    for (int k = 0; k < BK; ++k) {
        float a[TM], b[TN];
        *(float4*)&a[0] = *(const float4*)&As[k][rb];
        *(float4*)&a[4] = *(const float4*)&As[k][rb + 4];
        *(float4*)&b[0] = *(const float4*)&Bs[k][cb];
        *(float4*)&b[4] = *(const float4*)&Bs[k][cb + 4];
#pragma unroll
        for (int i = 0; i < TM; ++i)
#pragma unroll
            for (int j = 0; j < TN; ++j)
                acc[i][j] += a[i] * b[j];
    }
}

// ---------------------------------------------------------------------------
// Kernel 1: q/k/v = J @ W{q,k,v}.  grid.z selects the matrix.
// Rows with position >= traj_length are skipped for q (z=0) and v (z=2);
// k (z=1) is needed for ALL positions (full-row softmax denominator).
// ---------------------------------------------------------------------------
__global__ __launch_bounds__(NTHREADS, 2)
void proj_kernel(const float* __restrict__ J,
                 const float* __restrict__ Wq,
                 const float* __restrict__ Wk,
                 const float* __restrict__ Wv,
                 const int* __restrict__ tlen) {
    __shared__ float As[BK][LDS];
    __shared__ float Bs[BK][LDS];

    const int z  = blockIdx.z;
    const int m0 = blockIdx.y * BM;    // row in flattened [B*L]
    const int n0 = blockIdx.x * BN;
    const int b  = m0 / Ll;

    if (z != 1) {
        if ((m0 % Ll) >= tlen[b]) return;   // q/v rows beyond traj length unused
    }

    const float* W = (z == 0) ? Wq : (z == 1) ? Wk : Wv;
    float*       C = (z == 0) ? g_q : (z == 1) ? g_k : g_v;

    const int tid = threadIdx.x;
    const int rb  = (tid >> 4) * TM;
    const int cb  = (tid & 15) * TN;

    float acc[TM][TN] = {};

    for (int k0 = 0; k0 < Ee; k0 += BK) {
        load_tileA(J, Ee, m0, k0, As, tid);
        load_tileB(W, Oo, k0, n0, Bs, tid);
        __syncthreads();
        microkernel(As, Bs, rb, cb, acc);
        __syncthreads();
    }

#pragma unroll
    for (int i = 0; i < TM; ++i) {
        float* crow = C + (size_t)(m0 + rb + i) * Oo + n0 + cb;
#pragma unroll
        for (int j = 0; j < TN; j += 4) {
            float4 v = {acc[i][j], acc[i][j + 1], acc[i][j + 2], acc[i][j + 3]};
            *(float4*)(crow + j) = v;
        }
    }
}

// ---------------------------------------------------------------------------
// Kernel 2: scores[b] = q[b] @ k[b]^T + sum_K(delta).  NT GEMM per batch.
// Skips q-tiles entirely beyond traj length (also skips their delta read).
// ---------------------------------------------------------------------------
__global__ __launch_bounds__(NTHREADS, 2)
void scores_kernel(const float* __restrict__ delta,
                   const int* __restrict__ tlen) {
    __shared__ float As[BK][LDS];
    __shared__ float Bs[BK][LDS];

    const int b  = blockIdx.z;
    const int m0 = blockIdx.y * BM;
    const int n0 = blockIdx.x * BN;
    const int t  = tlen[b];
    if (m0 >= t) return;

    const float* Q  = g_q + (size_t)b * Ll * Oo;
    const float* Km = g_k + (size_t)b * Ll * Oo;

    const int tid = threadIdx.x;
    const int rb  = (tid >> 4) * TM;
    const int cb  = (tid & 15) * TN;

    float acc[TM][TN] = {};

    for (int k0 = 0; k0 < Oo; k0 += BK) {
        load_tileA(Q,  Oo, m0, k0, As, tid);
        load_tileA(Km, Oo, n0, k0, Bs, tid);  // NT: B tile loaded like A
        __syncthreads();
        microkernel(As, Bs, rb, cb, acc);
        __syncthreads();
    }

#pragma unroll
    for (int i = 0; i < TM; ++i) {
        const size_t m     = (size_t)(m0 + rb + i);
        const size_t rowix = ((size_t)b * Ll + m) * Ll + n0 + cb;
        const float4* dp   = (const float4*)(delta + rowix * 4);
        float*        sp   = g_s + rowix;
#pragma unroll
        for (int j = 0; j < TN; j += 4) {
            float4 d0 = dp[j + 0], d1 = dp[j + 1], d2 = dp[j + 2], d3 = dp[j + 3];
            float4 o;
            o.x = acc[i][j + 0] + (d0.x + d0.y) + (d0.z + d0.w);
            o.y = acc[i][j + 1] + (d1.x + d1.y) + (d1.z + d1.w);
            o.z = acc[i][j + 2] + (d2.x + d2.y) + (d2.z + d2.w);
            o.w = acc[i][j + 3] + (d3.x + d3.y) + (d3.z + d3.w);
            *(float4*)(sp + j) = o;
        }
    }
}

// ---------------------------------------------------------------------------
// Kernel 3: row softmax over full L (invalid keys INCLUDED in denominator),
// then post-softmax mask: zero cols >= t; rows >= t written as zeros.
// One block per (q, b) row; 256 threads x float4 = 1024 elements.
// ---------------------------------------------------------------------------
__global__ __launch_bounds__(NTHREADS)
void softmax_kernel(const int* __restrict__ tlen) {
    const int q = blockIdx.x;
    const int b = blockIdx.y;
    const int t = tlen[b];
    float4* row = (float4*)(g_s + ((size_t)b * Ll + q) * Ll);
    const int tid = threadIdx.x;

    if (q >= t) {                              // fully masked row
        row[tid] = make_float4(0.f, 0.f, 0.f, 0.f);
        return;
    }

    __shared__ float rmax[8], rsum[8];
    const int lane = tid & 31, wid = tid >> 5;

    float4 x = row[tid];
    float m = fmaxf(fmaxf(x.x, x.y), fmaxf(x.z, x.w));
#pragma unroll
    for (int o = 16; o; o >>= 1) m = fmaxf(m, __shfl_xor_sync(0xffffffffu, m, o));
    if (lane == 0) rmax[wid] = m;
    __syncthreads();
    m = rmax[0];
#pragma unroll
    for (int i = 1; i < 8; ++i) m = fmaxf(m, rmax[i]);

    float4 e;
    e.x = __expf(x.x - m);
    e.y = __expf(x.y - m);
    e.z = __expf(x.z - m);
    e.w = __expf(x.w - m);
    float s = (e.x + e.y) + (e.z + e.w);
#pragma unroll
    for (int o = 16; o; o >>= 1) s += __shfl_xor_sync(0xffffffffu, s, o);
    if (lane == 0) rsum[wid] = s;
    __syncthreads();
    s = rsum[0];
#pragma unroll
    for (int i = 1; i < 8; ++i) s += rsum[i];

    const float inv = 1.f / s;
    const int k0 = tid << 2;
    e.x = (k0 + 0 < t) ? e.x * inv : 0.f;
    e.y = (k0 + 1 < t) ? e.y * inv : 0.f;
    e.z = (k0 + 2 < t) ? e.z * inv : 0.f;
    e.w = (k0 + 3 < t) ? e.w * inv : 0.f;
    row[tid] = e;
}

// ---------------------------------------------------------------------------
// Kernel 4: out[b] = attn[b] @ v[b].  K-loop truncated at ceil16(t) (attn is
// zero beyond t). q-tiles >= t write zeros (d_out is poisoned).
// ---------------------------------------------------------------------------
__global__ __launch_bounds__(NTHREADS, 2)
void out_kernel(float* __restrict__ out, const int* __restrict__ tlen) {
    __shared__ float As[BK][LDS];
    __shared__ float Bs[BK][LDS];

    const int b  = blockIdx.z;
    const int m0 = blockIdx.y * BM;
    const int n0 = blockIdx.x * BN;
    const int t  = tlen[b];
    const int tid = threadIdx.x;

    float* C = out + (size_t)b * Ll * Oo;

    if (m0 >= t) {                             // fully masked tile -> zeros
        const float4 z4 = make_float4(0.f, 0.f, 0.f, 0.f);
#pragma unroll
        for (int s = 0; s < (BM * BN) / (NTHREADS * 4); ++s) {
            int ff = tid + s * NTHREADS;       // 0..4095 float4 slots
            int r  = ff >> 5;                  // 32 float4 per tile row
            int c4 = (ff & 31) << 2;
            *(float4*)(C + (size_t)(m0 + r) * Oo + n0 + c4) = z4;
        }
        return;
    }

    const float* A = g_s + (size_t)b * Ll * Ll;   // attn, lda = L
    const float* V = g_v + (size_t)b * Ll * Oo;

    const int rb = (tid >> 4) * TM;
    const int cb = (tid & 15) * TN;
    const int kend = (t + BK - 1) & ~(BK - 1);

    float acc[TM][TN] = {};

    for (int k0 = 0; k0 < kend; k0 += BK) {
        load_tileA(A, Ll, m0, k0, As, tid);
        load_tileB(V, Oo, k0, n0, Bs, tid);
        __syncthreads();
        microkernel(As, Bs, rb, cb, acc);
        __syncthreads();
    }

#pragma unroll
    for (int i = 0; i < TM; ++i) {
        float* crow = C + (size_t)(m0 + rb + i) * Oo + n0 + cb;
#pragma unroll
        for (int j = 0; j < TN; j += 4) {
            float4 v = {acc[i][j], acc[i][j + 1], acc[i][j + 2], acc[i][j + 3]};
            *(float4*)(crow + j) = v;
        }
    }
}

// ---------------------------------------------------------------------------
extern "C" void kernel_launch(void* const* d_in, const int* in_sizes, int n_in,
                              void* d_out, int out_size) {
    const float* J     = (const float*)d_in[0];   // joint_embedding [B,L,E]
    const float* delta = (const float*)d_in[1];   // delta_embedding [B,L,L,4]
    const float* Wq    = (const float*)d_in[2];   // [E,O]
    const float* Wk    = (const float*)d_in[3];
    const float* Wv    = (const float*)d_in[4];
    const int*   tlen  = (const int*)d_in[5];     // [B]
    float*       out   = (float*)d_out;           // [B,L,O] fp32

    proj_kernel<<<dim3(Oo / BN, (Bb * Ll) / BM, 3), NTHREADS>>>(J, Wq, Wk, Wv, tlen);
    scores_kernel<<<dim3(Ll / BN, Ll / BM, Bb), NTHREADS>>>(delta, tlen);
    softmax_kernel<<<dim3(Ll, Bb), NTHREADS>>>(tlen);
    out_kernel<<<dim3(Oo / BN, Ll / BM, Bb), NTHREADS>>>(out, tlen);
}

// round 5
// speedup vs baseline: 2.4972x; 2.4972x over previous
#include <cuda_runtime.h>
#include <cuda_fp16.h>
#include <cstdint>

// Problem constants
#define Bb 32
#define Ll 1024
#define Ee 512
#define Oo 512
#define BL (Bb * Ll)

// GEMM tiling: CTA 128x128x64, 8 warps of 64x32
#define TBM 128
#define TBN 128
#define TBK 64
#define GEMM_THREADS 256
#define PLANE 16384                  // one 128x64 fp16 plane (128B rows)
#define STAGE (4 * PLANE)            // Ahi, Alo, Bhi, Blo
#define DYNSM (2 * STAGE)            // 128 KB, double buffered

#define SMEM_SWIZZLE_128B(off) ((off) ^ (((off) >> 3) & 0x70))

__device__ __forceinline__ uint32_t smem_to_u32(const void* p) {
    uint32_t a;
    asm("{ .reg .u64 t; cvta.to.shared.u64 t, %1; cvt.u32.u64 %0, t; }" : "=r"(a) : "l"(p));
    return a;
}

#define CP_ASYNC16(dst, src) \
    asm volatile("cp.async.cg.shared.global [%0], [%1], 16;" :: "r"(dst), "l"(src))
#define CP_COMMIT() asm volatile("cp.async.commit_group;" ::: "memory")
#define CP_WAIT(N)  asm volatile("cp.async.wait_group %0;" :: "n"(N) : "memory")

#define LDSM_X4(r0, r1, r2, r3, a) \
    asm volatile("ldmatrix.sync.aligned.m8n8.x4.shared.b16 {%0,%1,%2,%3}, [%4];" \
                 : "=r"(r0), "=r"(r1), "=r"(r2), "=r"(r3) : "r"(a))

__device__ __forceinline__ void mma16816(float* c, const uint32_t* a, const uint32_t* b) {
    asm volatile(
        "mma.sync.aligned.m16n8k16.row.col.f32.f16.f16.f32 "
        "{%0,%1,%2,%3}, {%4,%5,%6,%7}, {%8,%9}, {%0,%1,%2,%3};"
        : "+f"(c[0]), "+f"(c[1]), "+f"(c[2]), "+f"(c[3])
        : "r"(a[0]), "r"(a[1]), "r"(a[2]), "r"(a[3]), "r"(b[0]), "r"(b[1]));
}

// ---------------------------------------------------------------------------
// Scratch (static __device__; zero-initialized at module load; no allocations)
// ---------------------------------------------------------------------------
__device__ __half g_J_hi[BL * Ee],  g_J_lo[BL * Ee];
__device__ __half g_Wt_hi[3 * Oo * Ee], g_Wt_lo[3 * Oo * Ee];
__device__ __half g_q_hi[BL * Oo],  g_q_lo[BL * Oo];
__device__ __half g_k_hi[BL * Oo],  g_k_lo[BL * Oo];
__device__ __half g_vT_hi[Bb * Oo * Ll], g_vT_lo[Bb * Oo * Ll];
__device__ float  g_s[(size_t)Bb * Ll * Ll];
__device__ __half g_at_hi[(size_t)Bb * Ll * Ll], g_at_lo[(size_t)Bb * Ll * Ll];

__device__ __forceinline__ void split2(float x, __half& hi, __half& lo) {
    hi = __float2half_rn(x);
    lo = __float2half_rn(x - __half2float(hi));
}
__device__ __forceinline__ uint32_t packh2(__half a, __half b) {
    __half2 h = __halves2half2(a, b);
    return *(uint32_t*)&h;
}

// ---------------------------------------------------------------------------
// Pre-pass kernels
// ---------------------------------------------------------------------------
__global__ void splitJ_kernel(const float* __restrict__ J) {
    const int n4 = (BL * Ee) / 4;
    for (int i = blockIdx.x * blockDim.x + threadIdx.x; i < n4; i += gridDim.x * blockDim.x) {
        float4 v = ((const float4*)J)[i];
        __half h0, h1, h2, h3, l0, l1, l2, l3;
        split2(v.x, h0, l0); split2(v.y, h1, l1); split2(v.z, h2, l2); split2(v.w, h3, l3);
        ((uint32_t*)g_J_hi)[2 * i]     = packh2(h0, h1);
        ((uint32_t*)g_J_hi)[2 * i + 1] = packh2(h2, h3);
        ((uint32_t*)g_J_lo)[2 * i]     = packh2(l0, l1);
        ((uint32_t*)g_J_lo)[2 * i + 1] = packh2(l2, l3);
    }
}

__global__ void splitW_kernel(const float* __restrict__ Wq,
                              const float* __restrict__ Wk,
                              const float* __restrict__ Wv) {
    __shared__ float t[32][33];
    const int z = blockIdx.z;
    const float* W = (z == 0) ? Wq : (z == 1) ? Wk : Wv;
    const int e0 = blockIdx.y * 32, o0 = blockIdx.x * 32;
    for (int r = threadIdx.y; r < 32; r += 8)
        t[r][threadIdx.x] = W[(e0 + r) * Oo + o0 + threadIdx.x];
    __syncthreads();
    for (int r = threadIdx.y; r < 32; r += 8) {
        float x = t[threadIdx.x][r];
        __half hi, lo; split2(x, hi, lo);
        const int idx = z * Oo * Ee + (o0 + r) * Ee + e0 + threadIdx.x;
        g_Wt_hi[idx] = hi;
        g_Wt_lo[idx] = lo;
    }
}

// ---------------------------------------------------------------------------
// GEMM machinery. A [M rows][K], B [N rows][K], both K-major fp16 hi/lo.
// C = Ah*Bh^T + Ah*Bl^T + Al*Bh^T, fp32 accum in registers.
// ---------------------------------------------------------------------------
__device__ __forceinline__ void load_stage(const __half* __restrict__ Ahi,
                                           const __half* __restrict__ Alo, int lda, int m0,
                                           const __half* __restrict__ Bhi,
                                           const __half* __restrict__ Blo, int ldb, int n0,
                                           int k0, uint32_t sb, int tid) {
#pragma unroll
    for (int s = 0; s < 4; ++s) {
        int ff = tid + s * GEMM_THREADS;       // 0..1023
        int row = ff >> 3, c8 = ff & 7;
        uint32_t d = SMEM_SWIZZLE_128B(row * 128 + c8 * 16);
        CP_ASYNC16(sb + 0 * PLANE + d, Ahi + (size_t)(m0 + row) * lda + k0 + c8 * 8);
        CP_ASYNC16(sb + 1 * PLANE + d, Alo + (size_t)(m0 + row) * lda + k0 + c8 * 8);
        CP_ASYNC16(sb + 2 * PLANE + d, Bhi + (size_t)(n0 + row) * ldb + k0 + c8 * 8);
        CP_ASYNC16(sb + 3 * PLANE + d, Blo + (size_t)(n0 + row) * ldb + k0 + c8 * 8);
    }
    CP_COMMIT();
}

__device__ __forceinline__ void mma_ktile(uint32_t sb, float acc[4][4][4],
                                          int wm, int wn, int lane) {
    const int mat = lane >> 3, tr = lane & 7;
#pragma unroll
    for (int ks = 0; ks < 4; ++ks) {
        uint32_t ah[4][4], al[4][4], bh[4][2], bl[4][2];
        const int acb = ks * 32 + (mat >> 1) * 16;
#pragma unroll
        for (int mf = 0; mf < 4; ++mf) {
            const int r = wm + mf * 16 + (mat & 1) * 8 + tr;
            const uint32_t off = SMEM_SWIZZLE_128B(r * 128 + acb);
            LDSM_X4(ah[mf][0], ah[mf][1], ah[mf][2], ah[mf][3], sb + 0 * PLANE + off);
            LDSM_X4(al[mf][0], al[mf][1], al[mf][2], al[mf][3], sb + 1 * PLANE + off);
        }
        const int bcb = ks * 32 + (mat & 1) * 16;
#pragma unroll
        for (int np = 0; np < 2; ++np) {
            const int r = wn + np * 16 + (mat >> 1) * 8 + tr;
            const uint32_t off = SMEM_SWIZZLE_128B(r * 128 + bcb);
            LDSM_X4(bh[2 * np][0], bh[2 * np][1], bh[2 * np + 1][0], bh[2 * np + 1][1],
                    sb + 2 * PLANE + off);
            LDSM_X4(bl[2 * np][0], bl[2 * np][1], bl[2 * np + 1][0], bl[2 * np + 1][1],
                    sb + 3 * PLANE + off);
        }
#pragma unroll
        for (int mf = 0; mf < 4; ++mf)
#pragma unroll
            for (int nf = 0; nf < 4; ++nf) {
                mma16816(acc[mf][nf], ah[mf], bh[nf]);
                mma16816(acc[mf][nf], ah[mf], bl[nf]);
                mma16816(acc[mf][nf], al[mf], bh[nf]);
            }
    }
}

__device__ __forceinline__ void gemm_run(const __half* Ahi, const __half* Alo, int lda, int m0,
                                         const __half* Bhi, const __half* Blo, int ldb, int n0,
                                         int nkt, uint32_t sm, float acc[4][4][4],
                                         int tid, int wm, int wn, int lane) {
    load_stage(Ahi, Alo, lda, m0, Bhi, Blo, ldb, n0, 0, sm, tid);
    for (int kt = 0; kt < nkt; ++kt) {
        if (kt + 1 < nkt) {
            load_stage(Ahi, Alo, lda, m0, Bhi, Blo, ldb, n0,
                       (kt + 1) * TBK, sm + ((kt + 1) & 1) * STAGE, tid);
            CP_WAIT(1);
        } else {
            CP_WAIT(0);
        }
        __syncthreads();
        mma_ktile(sm + (kt & 1) * STAGE, acc, wm, wn, lane);
        __syncthreads();
    }
}

#define GEMM_VARS()                                   \
    extern __shared__ char dynsm[];                   \
    const uint32_t sm_u32 = smem_to_u32(dynsm);       \
    const int tid  = threadIdx.x;                     \
    const int wid  = tid >> 5;                        \
    const int lane = tid & 31;                        \
    const int wm   = (wid & 1) * 64;                  \
    const int wn   = (wid >> 1) * 32;                 \
    const int g    = lane >> 2;                       \
    const int qi   = lane & 3;                        \
    float acc[4][4][4] = {};

// ---------------------------------------------------------------------------
// GEMM 1: q/k/v projection. z=0 q, z=1 k (all rows), z=2 v (transposed out).
// ---------------------------------------------------------------------------
__global__ __launch_bounds__(GEMM_THREADS, 1)
void proj_kernel(const int* __restrict__ tlen) {
    const int z  = blockIdx.z;
    const int m0 = blockIdx.y * TBM;
    const int n0 = blockIdx.x * TBN;
    const int b  = m0 / Ll;
    const int l0 = m0 % Ll;                 // sequence-local row base
    if (z != 1 && l0 >= tlen[b]) return;

    GEMM_VARS();

    gemm_run(g_J_hi, g_J_lo, Ee, m0,
             g_Wt_hi + z * Oo * Ee, g_Wt_lo + z * Oo * Ee, Ee, n0,
             Ee / TBK, sm_u32, acc, tid, wm, wn, lane);

    if (z != 2) {
        __half* Hh = (z == 0) ? g_q_hi : g_k_hi;
        __half* Hl = (z == 0) ? g_q_lo : g_k_lo;
#pragma unroll
        for (int mf = 0; mf < 4; ++mf)
#pragma unroll
            for (int nf = 0; nf < 4; ++nf) {
                const int col = n0 + wn + nf * 8 + 2 * qi;
#pragma unroll
                for (int hrow = 0; hrow < 2; ++hrow) {
                    const size_t m = m0 + wm + mf * 16 + g + hrow * 8;
                    float v0 = acc[mf][nf][2 * hrow], v1 = acc[mf][nf][2 * hrow + 1];
                    __half h0, h1, l0h, l1h;
                    split2(v0, h0, l0h); split2(v1, h1, l1h);
                    *(uint32_t*)(Hh + m * Oo + col) = packh2(h0, h1);
                    *(uint32_t*)(Hl + m * Oo + col) = packh2(l0h, l1h);
                }
            }
    } else {
        // transpose through SMEM: ts[n][m] (129-float pitch), then coalesced vT write
        float* ts = (float*)dynsm;
        const int ldm = 129;
#pragma unroll
        for (int mf = 0; mf < 4; ++mf)
#pragma unroll
            for (int nf = 0; nf < 4; ++nf) {
                const int col = wn + nf * 8 + 2 * qi;
#pragma unroll
                for (int hrow = 0; hrow < 2; ++hrow) {
                    const int mr = wm + mf * 16 + g + hrow * 8;
                    ts[(col + 0) * ldm + mr] = acc[mf][nf][2 * hrow];
                    ts[(col + 1) * ldm + mr] = acc[mf][nf][2 * hrow + 1];
                }
            }
        __syncthreads();
#pragma unroll
        for (int it = 0; it < 4; ++it) {
            const int orow = it * 32 + (tid >> 3);
            const int j0   = (tid & 7) * 16;
            const float* srow = ts + orow * ldm + j0;
            uint32_t hw[8], lw[8];
#pragma unroll
            for (int p = 0; p < 8; ++p) {
                __half h0, h1, lo0, lo1;
                split2(srow[2 * p], h0, lo0);
                split2(srow[2 * p + 1], h1, lo1);
                hw[p] = packh2(h0, h1);
                lw[p] = packh2(lo0, lo1);
            }
            // FIX (R3 bug): index with sequence-local l0, not global m0
            const size_t ob = ((size_t)b * Oo + n0 + orow) * Ll + l0 + j0;
            *(uint4*)(g_vT_hi + ob)     = make_uint4(hw[0], hw[1], hw[2], hw[3]);
            *(uint4*)(g_vT_hi + ob + 8) = make_uint4(hw[4], hw[5], hw[6], hw[7]);
            *(uint4*)(g_vT_lo + ob)     = make_uint4(lw[0], lw[1], lw[2], lw[3]);
            *(uint4*)(g_vT_lo + ob + 8) = make_uint4(lw[4], lw[5], lw[6], lw[7]);
        }
    }
}

// ---------------------------------------------------------------------------
// GEMM 2: scores = q x k^T + rowsum(delta) -> g_s fp32
// ---------------------------------------------------------------------------
__global__ __launch_bounds__(GEMM_THREADS, 1)
void scores_kernel(const float* __restrict__ delta, const int* __restrict__ tlen) {
    const int b  = blockIdx.z;
    const int m0 = blockIdx.y * TBM;
    const int n0 = blockIdx.x * TBN;
    if (m0 >= tlen[b]) return;

    GEMM_VARS();

    const size_t qb = (size_t)b * Ll * Oo;
    gemm_run(g_q_hi + qb, g_q_lo + qb, Oo, m0,
             g_k_hi + qb, g_k_lo + qb, Oo, n0,
             Oo / TBK, sm_u32, acc, tid, wm, wn, lane);

#pragma unroll
    for (int mf = 0; mf < 4; ++mf)
#pragma unroll
        for (int nf = 0; nf < 4; ++nf) {
            const int col = n0 + wn + nf * 8 + 2 * qi;
#pragma unroll
            for (int hrow = 0; hrow < 2; ++hrow) {
                const size_t r = m0 + wm + mf * 16 + g + hrow * 8;
                const size_t ix = ((size_t)b * Ll + r) * Ll + col;
                const float4 d0 = ((const float4*)delta)[ix];
                const float4 d1 = ((const float4*)delta)[ix + 1];
                float2 o;
                o.x = acc[mf][nf][2 * hrow]     + (d0.x + d0.y) + (d0.z + d0.w);
                o.y = acc[mf][nf][2 * hrow + 1] + (d1.x + d1.y) + (d1.z + d1.w);
                *(float2*)(g_s + ix) = o;
            }
        }
}

// ---------------------------------------------------------------------------
// Softmax over full row, post-mask, split attn to fp16 hi/lo.
// ---------------------------------------------------------------------------
__global__ __launch_bounds__(256)
void softmax_kernel(const int* __restrict__ tlen) {
    const int q = blockIdx.x, b = blockIdx.y;
    const int t = tlen[b];
    const size_t rowb = ((size_t)b * Ll + q) * Ll;
    const int tid = threadIdx.x;
    uint32_t* ah = (uint32_t*)(g_at_hi + rowb);
    uint32_t* al = (uint32_t*)(g_at_lo + rowb);

    if (q >= t) {
        ah[2 * tid] = 0u; ah[2 * tid + 1] = 0u;
        al[2 * tid] = 0u; al[2 * tid + 1] = 0u;
        return;
    }

    __shared__ float rmax[8], rsum[8];
    const int lane = tid & 31, wrp = tid >> 5;
    float4 x = ((const float4*)(g_s + rowb))[tid];

    float m = fmaxf(fmaxf(x.x, x.y), fmaxf(x.z, x.w));
#pragma unroll
    for (int o = 16; o; o >>= 1) m = fmaxf(m, __shfl_xor_sync(~0u, m, o));
    if (lane == 0) rmax[wrp] = m;
    __syncthreads();
    m = rmax[0];
#pragma unroll
    for (int i = 1; i < 8; ++i) m = fmaxf(m, rmax[i]);

    float4 e;
    e.x = __expf(x.x - m); e.y = __expf(x.y - m);
    e.z = __expf(x.z - m); e.w = __expf(x.w - m);
    float s = (e.x + e.y) + (e.z + e.w);
#pragma unroll
    for (int o = 16; o; o >>= 1) s += __shfl_xor_sync(~0u, s, o);
    if (lane == 0) rsum[wrp] = s;
    __syncthreads();
    s = rsum[0];
#pragma unroll
    for (int i = 1; i < 8; ++i) s += rsum[i];

    const float inv = 1.f / s;
    const int k0 = tid << 2;
    e.x = (k0 + 0 < t) ? e.x * inv : 0.f;
    e.y = (k0 + 1 < t) ? e.y * inv : 0.f;
    e.z = (k0 + 2 < t) ? e.z * inv : 0.f;
    e.w = (k0 + 3 < t) ? e.w * inv : 0.f;

    __half h0, h1, h2, h3, l0, l1, l2, l3;
    split2(e.x, h0, l0); split2(e.y, h1, l1); split2(e.z, h2, l2); split2(e.w, h3, l3);
    ah[2 * tid]     = packh2(h0, h1);
    ah[2 * tid + 1] = packh2(h2, h3);
    al[2 * tid]     = packh2(l0, l1);
    al[2 * tid + 1] = packh2(l2, l3);
}

// ---------------------------------------------------------------------------
// GEMM 3: out = attn x vT^T (NT, K = key position, truncated at ceil64(t))
// ---------------------------------------------------------------------------
__global__ __launch_bounds__(GEMM_THREADS, 1)
void av_kernel(float* __restrict__ out, const int* __restrict__ tlen) {
    const int b  = blockIdx.z;
    const int m0 = blockIdx.y * TBM;
    const int n0 = blockIdx.x * TBN;
    const int t  = tlen[b];
    float* C = out + (size_t)b * Ll * Oo;

    if (m0 >= t) {
        const float4 z4 = make_float4(0.f, 0.f, 0.f, 0.f);
        const int tid0 = threadIdx.x;
#pragma unroll
        for (int s = 0; s < (TBM * TBN) / (GEMM_THREADS * 4); ++s) {
            int ff = tid0 + s * GEMM_THREADS;
            int r = ff >> 5, c4 = (ff & 31) << 2;
            *(float4*)(C + (size_t)(m0 + r) * Oo + n0 + c4) = z4;
        }
        return;
    }

    GEMM_VARS();

    const size_t ab = (size_t)b * Ll * Ll;
    const size_t vb = (size_t)b * Oo * Ll;
    const int nkt = (t + TBK - 1) / TBK;
    gemm_run(g_at_hi + ab, g_at_lo + ab, Ll, m0,
             g_vT_hi + vb, g_vT_lo + vb, Ll, n0,
             nkt, sm_u32, acc, tid, wm, wn, lane);

#pragma unroll
    for (int mf = 0; mf < 4; ++mf)
#pragma unroll
        for (int nf = 0; nf < 4; ++nf) {
            const int col = n0 + wn + nf * 8 + 2 * qi;
#pragma unroll
            for (int hrow = 0; hrow < 2; ++hrow) {
                const size_t r = m0 + wm + mf * 16 + g + hrow * 8;
                float2 o = {acc[mf][nf][2 * hrow], acc[mf][nf][2 * hrow + 1]};
                *(float2*)(C + r * Oo + col) = o;
            }
        }
}

// ---------------------------------------------------------------------------
extern "C" void kernel_launch(void* const* d_in, const int* in_sizes, int n_in,
                              void* d_out, int out_size) {
    const float* J     = (const float*)d_in[0];
    const float* delta = (const float*)d_in[1];
    const float* Wq    = (const float*)d_in[2];
    const float* Wk    = (const float*)d_in[3];
    const float* Wv    = (const float*)d_in[4];
    const int*   tlen  = (const int*)d_in[5];
    float*       out   = (float*)d_out;

    cudaFuncSetAttribute(proj_kernel,   cudaFuncAttributeMaxDynamicSharedMemorySize, DYNSM);
    cudaFuncSetAttribute(scores_kernel, cudaFuncAttributeMaxDynamicSharedMemorySize, DYNSM);
    cudaFuncSetAttribute(av_kernel,     cudaFuncAttributeMaxDynamicSharedMemorySize, DYNSM);

    splitJ_kernel<<<8192, 256>>>(J);
    splitW_kernel<<<dim3(16, 16, 3), dim3(32, 8)>>>(Wq, Wk, Wv);
    proj_kernel<<<dim3(Oo / TBN, BL / TBM, 3), GEMM_THREADS, DYNSM>>>(tlen);
    scores_kernel<<<dim3(Ll / TBN, Ll / TBM, Bb), GEMM_THREADS, DYNSM>>>(delta, tlen);
    softmax_kernel<<<dim3(Ll, Bb), 256>>>(tlen);
    av_kernel<<<dim3(Oo / TBN, Ll / TBM, Bb), GEMM_THREADS, DYNSM>>>(out, tlen);
}